// round 17
// baseline (speedup 1.0000x reference)
#include <cuda_runtime.h>
#include <cuda_bf16.h>

#define HID 256
#define GAMMA_F 12.0f
#define BATCH 8
#define NE_MAX 100000

__device__ float g_scores[BATCH * NE_MAX];   // S[e*8+b], 3.2MB (L2-resident)

// ---------------------------------------------------------------------------
// Phase 1 (R13 champion, verbatim): warp per contiguous chunk; 2 rows/iter +
// 2-row lookahead. hrs2[j] on lane l = 2*(head+rel) of batch (j ^ perm(l)),
// perm=(l>>2)&7, making every fold stage a pure SHFL+FADD (no FSEL).
// ---------------------------------------------------------------------------
__global__ void __launch_bounds__(256, 2)
score_kernel(const float* __restrict__ ent,
             const float* __restrict__ rel,
             const int*   __restrict__ pos,
             float*       __restrict__ scores,
             int ne)
{
    const int lane = threadIdx.x & 31;
    const int warp = threadIdx.x >> 5;
    const int perm = (lane >> 2) & 7;

    float hrs2[BATCH][8];
#pragma unroll
    for (int j = 0; j < BATCH; j++) {
        const int b = j ^ perm;
        const int hidx = pos[b * 3 + 0];
        const int ridx = pos[b * 3 + 1];
        const float4* h4 = reinterpret_cast<const float4*>(ent + (size_t)hidx * HID);
        const float4* r4 = reinterpret_cast<const float4*>(rel + (size_t)ridx * HID);
        float4 h0 = h4[lane * 2], h1 = h4[lane * 2 + 1];
        float4 r0 = r4[lane * 2], r1 = r4[lane * 2 + 1];
        hrs2[j][0] = 2.0f * (h0.x + r0.x);  hrs2[j][1] = 2.0f * (h0.y + r0.y);
        hrs2[j][2] = 2.0f * (h0.z + r0.z);  hrs2[j][3] = 2.0f * (h0.w + r0.w);
        hrs2[j][4] = 2.0f * (h1.x + r1.x);  hrs2[j][5] = 2.0f * (h1.y + r1.y);
        hrs2[j][6] = 2.0f * (h1.z + r1.z);  hrs2[j][7] = 2.0f * (h1.w + r1.w);
    }

    const int gw = blockIdx.x * 8 + warp;
    const int W  = gridDim.x * 8;
    const int per   = ne / W;
    const int rem   = ne % W;
    const int start = gw * per + (gw < rem ? gw : rem);
    const int end   = start + per + (gw < rem ? 1 : 0);

    float eA[8], eB[8], pA[8], pB[8];

    auto ld = [&](int row, float* d) {
        const float4* er = reinterpret_cast<const float4*>(ent + (size_t)row * HID);
        float4 x = er[lane * 2], y = er[lane * 2 + 1];
        d[0]=x.x; d[1]=x.y; d[2]=x.z; d[3]=x.w;
        d[4]=y.x; d[5]=y.y; d[6]=y.z; d[7]=y.w;
    };

    if (start     < end) ld(start, eA);
    if (start + 1 < end) ld(start + 1, eB);

    for (int row = start; row < end; row += 2) {
        const bool hasB = row + 1 < end;
        if (row + 2 < end) ld(row + 2, pA);   // lookahead
        if (row + 3 < end) ld(row + 3, pB);

        float vA[BATCH], vB[BATCH];
#pragma unroll
        for (int j = 0; j < BATCH; j++) {
            float a = fabsf(__fmaf_rn(eA[0], -2.0f, hrs2[j][0]));
            float b = fabsf(__fmaf_rn(eB[0], -2.0f, hrs2[j][0]));
#pragma unroll
            for (int k = 1; k < 8; k++) {
                a += fabsf(__fmaf_rn(eA[k], -2.0f, hrs2[j][k]));
                b += fabsf(__fmaf_rn(eB[k], -2.0f, hrs2[j][k]));
            }
            vA[j] = a;  vB[j] = b;
        }

#pragma unroll
        for (int j = 0; j < 4; j++) {
            vA[j] += __shfl_xor_sync(0xFFFFFFFFu, vA[j + 4], 16);
            vB[j] += __shfl_xor_sync(0xFFFFFFFFu, vB[j + 4], 16);
        }
#pragma unroll
        for (int j = 0; j < 2; j++) {
            vA[j] += __shfl_xor_sync(0xFFFFFFFFu, vA[j + 2], 8);
            vB[j] += __shfl_xor_sync(0xFFFFFFFFu, vB[j + 2], 8);
        }
        vA[0] += __shfl_xor_sync(0xFFFFFFFFu, vA[1], 4);
        vB[0] += __shfl_xor_sync(0xFFFFFFFFu, vB[1], 4);
        vA[0] += __shfl_xor_sync(0xFFFFFFFFu, vA[0], 2);
        vB[0] += __shfl_xor_sync(0xFFFFFFFFu, vB[0], 2);
        vA[0] += __shfl_xor_sync(0xFFFFFFFFu, vA[0], 1);
        vB[0] += __shfl_xor_sync(0xFFFFFFFFu, vB[0], 1);

        if ((lane & 3) == 0) {
            scores[(size_t)row * BATCH + perm] = __fmaf_rn(vA[0], -0.5f, GAMMA_F);
            if (hasB)
                scores[(size_t)(row + 1) * BATCH + perm] =
                    __fmaf_rn(vB[0], -0.5f, GAMMA_F);
        }

#pragma unroll
        for (int k = 0; k < 8; k++) { eA[k] = pA[k]; eB[k] = pB[k]; }
    }
}

// ---------------------------------------------------------------------------
// Phase 2: out[b][n] = scores[neg[b][n]*8 + b]. int2 per thread -> 400k
// threads (full machine occupancy) for max resident MLP.
// ---------------------------------------------------------------------------
__global__ void __launch_bounds__(128)
gather_kernel(const float* __restrict__ scores,
              const int*   __restrict__ neg,
              float*       __restrict__ out,
              int nneg)
{
    const int b = blockIdx.y;
    const int t = blockIdx.x * 128 + threadIdx.x;
    const int n2 = nneg >> 1;

    if (t < n2) {
        const int2 idx = reinterpret_cast<const int2*>(neg + (size_t)b * nneg)[t];
        float2 r;
        r.x = __ldg(scores + (size_t)idx.x * BATCH + b);
        r.y = __ldg(scores + (size_t)idx.y * BATCH + b);
        reinterpret_cast<float2*>(out + (size_t)b * nneg)[t] = r;
    }
    // Scalar tail (nneg odd), handled by thread 0 of block 0.
    if ((nneg & 1) && blockIdx.x == 0 && threadIdx.x == 0) {
        const int n = nneg - 1;
        out[(size_t)b * nneg + n] =
            __ldg(scores + (size_t)neg[(size_t)b * nneg + n] * BATCH + b);
    }
}

extern "C" void kernel_launch(void* const* d_in, const int* in_sizes, int n_in,
                              void* d_out, int out_size)
{
    const float* ent = (const float*)d_in[0];  // [NE, 256] f32
    const float* rel = (const float*)d_in[1];  // [NR, 256] f32
    const int*   pos = (const int*)d_in[2];    // [B, 3] i32
    const int*   neg = (const int*)d_in[3];    // [B, N] i32
    float*       out = (float*)d_out;          // [B, N] f32

    const int batch = in_sizes[2] / 3;         // 8
    const int nneg  = in_sizes[3] / batch;     // 100000
    const int ne    = in_sizes[0] / HID;       // 100000
    (void)batch;

    float* scores;
    cudaGetSymbolAddress((void**)&scores, g_scores);

    score_kernel<<<296, 256>>>(ent, rel, pos, scores, ne);

    const int n2 = nneg / 2;
    dim3 g2((n2 + 127) / 128, BATCH);
    gather_kernel<<<g2, 128>>>(scores, neg, out, nneg);
}